// round 4
// baseline (speedup 1.0000x reference)
#include <cuda_runtime.h>
#include <cstdint>
#include <cstddef>

#define BB 8
#define SS 2048
#define TT 1024
#define EE 1024
#define HH 16
#define DD 64
#define CC 768

// Scratch (device globals: allocation-free rule)
__device__ float g_q [(size_t)BB*HH*SS*DD];   // [B,H,S,D]  64 MB
__device__ float g_k [(size_t)BB*HH*DD*TT];   // [B,H,D,T]  32 MB
__device__ float g_v [(size_t)BB*HH*TT*DD];   // [B,H,T,D]  32 MB
__device__ float g_ao[(size_t)BB*SS*EE];      // attn out [B,S,E] 64 MB

// ---- packed f32x2 helpers (Blackwell: doubles fp32 FMA rate; ptxas won't auto-fuse) ----
__device__ __forceinline__ unsigned long long pack2(float lo, float hi) {
    unsigned long long r;
    asm("mov.b64 %0, {%1, %2};" : "=l"(r) : "f"(lo), "f"(hi));
    return r;
}
__device__ __forceinline__ void unpack2(unsigned long long v, float& lo, float& hi) {
    asm("mov.b64 {%0, %1}, %2;" : "=f"(lo), "=f"(hi) : "l"(v));
}
__device__ __forceinline__ void ffma2(unsigned long long& d, unsigned long long a, unsigned long long b) {
    asm("fma.rn.f32x2 %0, %1, %2, %0;" : "+l"(d) : "l"(a), "l"(b));
}

// ============================================================================
// Generic GEMM: C[M,N] = A[M,K] @ W[K,N] + bias, with head-remapped output.
// 64x64 CTA tile, 256 threads, 4x4 micro-tile per thread, K-chunk 16.
// mode 0: plain row-major [M,N]
// mode 1: out[((b*H + h)*len + s)*D + d]   (Q, V layouts)
// mode 2: out[((b*H + h)*D + d)*T + s]     (K stored d-major)
// ============================================================================
__global__ __launch_bounds__(256) void gemm_bias_kernel(
    const float* __restrict__ A, const float* __restrict__ W,
    const float* __restrict__ bias, float* __restrict__ Cout,
    int M, int K, int N, int len, int mode)
{
    __shared__ __align__(16) float As[16][65];  // As[k][m], pad 65 -> conflict-free transposed store
    __shared__ __align__(16) float Bs[16][68];  // Bs[k][n], pad 68 keeps 16B alignment

    const int tid = threadIdx.x;
    const int tx = tid & 15;         // n-dim (x4)
    const int ty = tid >> 4;         // m-dim (x4)
    const int tm = blockIdx.y << 6;
    const int tn = blockIdx.x << 6;

    unsigned long long acc[4][2];
#pragma unroll
    for (int i = 0; i < 4; i++) { acc[i][0] = 0ULL; acc[i][1] = 0ULL; }

    const int la_r = tid >> 2;            // 0..63  row (m) of A tile
    const int la_c = (tid & 3) << 2;      // 0,4,8,12 k offset
    const float* Aptr = A + (size_t)(tm + la_r) * K + la_c;
    const float* Wptr = W + (size_t)ty * N + tn + (tx << 2);   // ty = k-row of B tile

    for (int k0 = 0; k0 < K; k0 += 16) {
        float4 av = *(const float4*)(Aptr + k0);
        float4 bv = *(const float4*)(Wptr + (size_t)k0 * N);
        As[la_c + 0][la_r] = av.x;
        As[la_c + 1][la_r] = av.y;
        As[la_c + 2][la_r] = av.z;
        As[la_c + 3][la_r] = av.w;
        *(float4*)&Bs[ty][tx << 2] = bv;
        __syncthreads();
#pragma unroll
        for (int kk = 0; kk < 16; kk++) {
            float a0 = As[kk][(ty << 2) + 0];
            float a1 = As[kk][(ty << 2) + 1];
            float a2 = As[kk][(ty << 2) + 2];
            float a3 = As[kk][(ty << 2) + 3];
            ulonglong2 bb = *(const ulonglong2*)&Bs[kk][tx << 2];
            unsigned long long Ax;
            Ax = pack2(a0, a0); ffma2(acc[0][0], Ax, bb.x); ffma2(acc[0][1], Ax, bb.y);
            Ax = pack2(a1, a1); ffma2(acc[1][0], Ax, bb.x); ffma2(acc[1][1], Ax, bb.y);
            Ax = pack2(a2, a2); ffma2(acc[2][0], Ax, bb.x); ffma2(acc[2][1], Ax, bb.y);
            Ax = pack2(a3, a3); ffma2(acc[3][0], Ax, bb.x); ffma2(acc[3][1], Ax, bb.y);
        }
        __syncthreads();
    }

#pragma unroll
    for (int i = 0; i < 4; i++) {
        int row = tm + (ty << 2) + i;
#pragma unroll
        for (int j2 = 0; j2 < 2; j2++) {
            float v0, v1;
            unpack2(acc[i][j2], v0, v1);
            int col = tn + (tx << 2) + (j2 << 1);
            v0 += bias[col];
            v1 += bias[col + 1];
            if (mode == 0) {
                Cout[(size_t)row * N + col]     = v0;
                Cout[(size_t)row * N + col + 1] = v1;
            } else {
                int b_ = row / len, s_ = row - b_ * len;
                int h0 = col >> 6, d0 = col & 63;   // col even -> col,col+1 same head
                if (mode == 1) {
                    float* p = Cout + (((size_t)b_ * HH + h0) * len + s_) * DD + d0;
                    p[0] = v0; p[1] = v1;
                } else {
                    float* p = Cout + (((size_t)b_ * HH + h0) * DD + d0) * TT + s_;
                    p[0] = v0; p[TT] = v1;
                }
            }
        }
    }
}

// ============================================================================
// Attention: one CTA per (b, h, 32-row s-tile). Full 32x1024 score tile in
// dynamic SMEM (stride 1025 = conflict-free phase-3 A-reads). Softmax per
// warp-row, avg_attn accumulated via atomicAdd (1/H factor).
// ============================================================================
#define SSTR 1025
#define ATT_SMEM_FLOATS (32 * SSTR + 64 * 33 + 64 * 68)
#define ATT_SMEM_BYTES  (ATT_SMEM_FLOATS * 4)

__global__ __launch_bounds__(256) void attn_kernel(
    const float* __restrict__ q, const float* __restrict__ kdt,
    const float* __restrict__ v, float* __restrict__ ao,
    float* __restrict__ avg)
{
    extern __shared__ float smem[];
    float* sS  = smem;                 // [32][1025] scores / probs
    float* sQ  = smem + 32 * SSTR;     // [64][33]  q transposed: sQ[d*33+s]
    float* sKV = sQ + 64 * 33;         // [64][68]  k chunk (d-major) / v chunk (t-major)

    const int tid = threadIdx.x;
    const int tilesPerHead = SS / 32;                       // 64
    const int bh = blockIdx.x / tilesPerHead;               // 0..B*H-1
    const int st = (blockIdx.x % tilesPerHead) * 32;
    const int b_ = bh / HH;
    const int h_ = bh - b_ * HH;

    const float* qbase = q   + ((size_t)bh * SS + st) * DD;
    const float* kbase = kdt + (size_t)bh * DD * TT;
    const float* vbase = v   + (size_t)bh * TT * DD;

    // Load Q tile [32,64] transposed into sQ[d][s]
#pragma unroll
    for (int i = 0; i < 2; i++) {
        int idx = tid + i * 256;           // 512 float4s = 32 rows x 16
        int ss_ = idx >> 4;
        int d4  = (idx & 15) << 2;
        float4 qv = *(const float4*)(qbase + (size_t)ss_ * DD + d4);
        sQ[(d4 + 0) * 33 + ss_] = qv.x;
        sQ[(d4 + 1) * 33 + ss_] = qv.y;
        sQ[(d4 + 2) * 33 + ss_] = qv.z;
        sQ[(d4 + 3) * 33 + ss_] = qv.w;
    }

    const int tx = tid & 15;   // t (or d) dim, x4
    const int ty = tid >> 4;   // s dim, x2

    // ---------------- Phase 1: scores = Q @ K^T * 1/sqrt(D) ----------------
    for (int c = 0; c < TT / 64; c++) {
        __syncthreads();
        // K chunk: kdt is [d][t] so loads are coalesced and stores conflict-free
#pragma unroll
        for (int i = 0; i < 4; i++) {
            int idx = tid + i * 256;        // 1024 float4s = 64 d x 16
            int dd = idx >> 4;
            int t4 = (idx & 15) << 2;
            float4 kv = *(const float4*)(kbase + (size_t)dd * TT + c * 64 + t4);
            *(float4*)&sKV[dd * 68 + t4] = kv;
        }
        __syncthreads();
        unsigned long long acc[2][2] = {{0ULL, 0ULL}, {0ULL, 0ULL}};
#pragma unroll
        for (int kk = 0; kk < 64; kk++) {
            float a0 = sQ[kk * 33 + (ty << 1)];
            float a1 = sQ[kk * 33 + (ty << 1) + 1];
            ulonglong2 bb = *(const ulonglong2*)&sKV[kk * 68 + (tx << 2)];
            unsigned long long Ax;
            Ax = pack2(a0, a0); ffma2(acc[0][0], Ax, bb.x); ffma2(acc[0][1], Ax, bb.y);
            Ax = pack2(a1, a1); ffma2(acc[1][0], Ax, bb.x); ffma2(acc[1][1], Ax, bb.y);
        }
        const float scale = 0.125f;   // 1/sqrt(64)
#pragma unroll
        for (int i = 0; i < 2; i++) {
            float v0, v1, v2, v3;
            unpack2(acc[i][0], v0, v1);
            unpack2(acc[i][1], v2, v3);
            float* p = sS + ((ty << 1) + i) * SSTR + c * 64 + (tx << 2);
            p[0] = v0 * scale; p[1] = v1 * scale; p[2] = v2 * scale; p[3] = v3 * scale;
        }
    }
    __syncthreads();

    // ---------------- Phase 2: softmax rows + avg_attn accumulation --------
    {
        const int warp = tid >> 5;
        const int lane = tid & 31;
#pragma unroll
        for (int r = 0; r < 4; r++) {
            int row = (warp << 2) + r;
            float* srow = sS + row * SSTR;
            float m = -1e30f;
            for (int t = lane; t < TT; t += 32) m = fmaxf(m, srow[t]);
#pragma unroll
            for (int off = 16; off; off >>= 1) m = fmaxf(m, __shfl_xor_sync(0xffffffffu, m, off));
            float sum = 0.f;
            for (int t = lane; t < TT; t += 32) {
                float e = __expf(srow[t] - m);
                srow[t] = e;
                sum += e;
            }
#pragma unroll
            for (int off = 16; off; off >>= 1) sum += __shfl_xor_sync(0xffffffffu, sum, off);
            float inv  = 1.0f / sum;
            float invh = inv * (1.0f / (float)HH);
            float* arow = avg + ((size_t)b_ * SS + st + row) * TT;
            for (int t = lane; t < TT; t += 32) {
                float e = srow[t];
                srow[t] = e * inv;
                atomicAdd(&arow[t], e * invh);
            }
        }
    }

    // ---------------- Phase 3: out = P @ V ---------------------------------
    unsigned long long oacc[2][2] = {{0ULL, 0ULL}, {0ULL, 0ULL}};
    for (int c = 0; c < TT / 64; c++) {
        __syncthreads();   // also joins all warps after softmax on first iter
#pragma unroll
        for (int i = 0; i < 4; i++) {
            int idx = tid + i * 256;
            int tt_ = idx >> 4;
            int d4  = (idx & 15) << 2;
            float4 vv = *(const float4*)(vbase + (size_t)(c * 64 + tt_) * DD + d4);
            *(float4*)&sKV[tt_ * 68 + d4] = vv;
        }
        __syncthreads();
#pragma unroll
        for (int kk = 0; kk < 64; kk++) {
            float a0 = sS[((ty << 1) + 0) * SSTR + c * 64 + kk];
            float a1 = sS[((ty << 1) + 1) * SSTR + c * 64 + kk];
            ulonglong2 bb = *(const ulonglong2*)&sKV[kk * 68 + (tx << 2)];
            unsigned long long Ax;
            Ax = pack2(a0, a0); ffma2(oacc[0][0], Ax, bb.x); ffma2(oacc[0][1], Ax, bb.y);
            Ax = pack2(a1, a1); ffma2(oacc[1][0], Ax, bb.x); ffma2(oacc[1][1], Ax, bb.y);
        }
    }
#pragma unroll
    for (int i = 0; i < 2; i++) {
        float v0, v1, v2, v3;
        unpack2(oacc[i][0], v0, v1);
        unpack2(oacc[i][1], v2, v3);
        int s_ = st + (ty << 1) + i;
        float* p = ao + ((size_t)b_ * SS + s_) * EE + h_ * DD + (tx << 2);
        *(float4*)p = make_float4(v0, v1, v2, v3);
    }
}

// ============================================================================
// Launch
// ============================================================================
extern "C" void kernel_launch(void* const* d_in, const int* in_sizes, int n_in,
                              void* d_out, int out_size)
{
    const float* x   = (const float*)d_in[0];
    const float* enc = (const float*)d_in[1];
    const float* Wq  = (const float*)d_in[2];
    const float* bq  = (const float*)d_in[3];
    const float* Wk  = (const float*)d_in[4];
    const float* bk  = (const float*)d_in[5];
    const float* Wv  = (const float*)d_in[6];
    const float* bv  = (const float*)d_in[7];
    const float* Wo  = (const float*)d_in[8];
    const float* bo  = (const float*)d_in[9];

    float* out = (float*)d_out;                       // [B,S,E]
    float* avg = out + (size_t)BB * SS * EE;          // [B,S,T]

    float *qp, *kp, *vp, *aop;
    cudaGetSymbolAddress((void**)&qp,  g_q);
    cudaGetSymbolAddress((void**)&kp,  g_k);
    cudaGetSymbolAddress((void**)&vp,  g_v);
    cudaGetSymbolAddress((void**)&aop, g_ao);

    cudaFuncSetAttribute(attn_kernel, cudaFuncAttributeMaxDynamicSharedMemorySize, ATT_SMEM_BYTES);

    // Zero avg_attn region (d_out is poisoned), then accumulate via atomics.
    cudaMemsetAsync(avg, 0, (size_t)BB * SS * TT * sizeof(float));

    // Q = x @ Wq + bq        -> [B,H,S,D]
    gemm_bias_kernel<<<dim3(EE / 64, (BB * SS) / 64), 256>>>(x,   Wq, bq, qp,  BB * SS, EE, EE, SS, 1);
    // K = enc @ Wk + bk      -> [B,H,D,T] (d-major for conflict-free attention loads)
    gemm_bias_kernel<<<dim3(EE / 64, (BB * TT) / 64), 256>>>(enc, Wk, bk, kp,  BB * TT, CC, EE, TT, 2);
    // V = enc @ Wv + bv      -> [B,H,T,D]
    gemm_bias_kernel<<<dim3(EE / 64, (BB * TT) / 64), 256>>>(enc, Wv, bv, vp,  BB * TT, CC, EE, TT, 1);
    // attention + avg_attn
    attn_kernel<<<BB * HH * (SS / 32), 256, ATT_SMEM_BYTES>>>(qp, kp, vp, aop, avg);
    // out = attn_out @ Wo + bo  (plain [B*S, E])
    gemm_bias_kernel<<<dim3(EE / 64, (BB * SS) / 64), 256>>>(aop, Wo, bo, out, BB * SS, EE, EE, 0, 0);
}

// round 5
// speedup vs baseline: 1.2970x; 1.2970x over previous
#include <cuda_runtime.h>
#include <cstdint>
#include <cstddef>

#define BB 8
#define SS 2048
#define TT 1024
#define EE 1024
#define HH 16
#define DD 64
#define CC 768

// Scratch (device globals: allocation-free rule)
__device__ float  g_q   [(size_t)BB*HH*SS*DD];   // [B,H,S,D]  64 MB
__device__ float  g_k   [(size_t)BB*HH*DD*TT];   // [B,H,D,T]  32 MB
__device__ float  g_v   [(size_t)BB*HH*TT*DD];   // [B,H,T,D]  32 MB
__device__ float  g_ao  [(size_t)BB*SS*EE];      // attn out [B,S,E] 64 MB
__device__ float  g_praw[(size_t)BB*HH*SS*TT];   // raw scaled scores [B,H,S,T] 1 GiB
__device__ float2 g_stat[(size_t)BB*HH*SS];      // per-row (m, invZ/H) 2 MB

// ---- packed f32x2 helpers ----
__device__ __forceinline__ unsigned long long pack2(float lo, float hi) {
    unsigned long long r;
    asm("mov.b64 %0, {%1, %2};" : "=l"(r) : "f"(lo), "f"(hi));
    return r;
}
__device__ __forceinline__ void unpack2(unsigned long long v, float& lo, float& hi) {
    asm("mov.b64 {%0, %1}, %2;" : "=f"(lo), "=f"(hi) : "l"(v));
}
__device__ __forceinline__ void ffma2(unsigned long long& d, unsigned long long a, unsigned long long b) {
    asm("fma.rn.f32x2 %0, %1, %2, %0;" : "+l"(d) : "l"(a), "l"(b));
}
__device__ __forceinline__ void fmul2(unsigned long long& d, unsigned long long a) {
    asm("mul.rn.f32x2 %0, %0, %1;" : "+l"(d) : "l"(a));
}

// ============================================================================
// GEMM v2: C[M,N] = A[M,K] @ W[K,N] + bias, head-remapped output.
// 128x64 CTA tile, 256 threads, 8(m)x4(n) micro-tile, K-chunk 32.
// A stored DUPLICATED in smem: As2[k][2m]=As2[k][2m+1]=a  -> LDS.64 gives (a,a)
// directly, zero mov.b64 packs in the inner loop. B read as natural f32x2
// pairs via LDS.128.
// mode 0: plain row-major [M,N]
// mode 1: out[((b*H + h)*len + s)*D + d]   (Q, V layouts)
// mode 2: out[((b*H + h)*D + d)*T + s]     (K stored d-major)
// ============================================================================
__global__ __launch_bounds__(256) void gemm_bias_kernel(
    const float* __restrict__ A, const float* __restrict__ W,
    const float* __restrict__ bias, float* __restrict__ Cout,
    int M, int K, int N, int len, int mode)
{
    __shared__ __align__(16) float As2[32][258];  // [k][2m] duplicated, stride even
    __shared__ __align__(16) float Bs [32][68];   // [k][n]

    const int tid = threadIdx.x;
    const int tx = tid & 15;          // n-dim (x4)
    const int ty = tid >> 4;          // m-dim (x8)
    const int tm = blockIdx.y << 7;
    const int tn = blockIdx.x << 6;

    unsigned long long acc[8][2];
#pragma unroll
    for (int i = 0; i < 8; i++) { acc[i][0] = 0ULL; acc[i][1] = 0ULL; }

    for (int k0 = 0; k0 < K; k0 += 32) {
        // Load A tile 128 x 32 (1024 float4), store duplicated-transposed.
#pragma unroll
        for (int i = 0; i < 4; i++) {
            int idx = tid + i * 256;
            int m  = idx >> 3;             // 0..127
            int kb = (idx & 7) << 2;       // 0..28
            float4 av = *(const float4*)(A + (size_t)(tm + m) * K + k0 + kb);
            *(float2*)&As2[kb + 0][m << 1] = make_float2(av.x, av.x);
            *(float2*)&As2[kb + 1][m << 1] = make_float2(av.y, av.y);
            *(float2*)&As2[kb + 2][m << 1] = make_float2(av.z, av.z);
            *(float2*)&As2[kb + 3][m << 1] = make_float2(av.w, av.w);
        }
        // Load B tile 32 x 64 (512 float4)
#pragma unroll
        for (int i = 0; i < 2; i++) {
            int idx = tid + i * 256;
            int kb = idx >> 4;             // 0..31
            int nf = (idx & 15) << 2;      // 0..60
            *(float4*)&Bs[kb][nf] = *(const float4*)(W + (size_t)(k0 + kb) * N + tn + nf);
        }
        __syncthreads();
#pragma unroll
        for (int kk = 0; kk < 32; kk++) {
            ulonglong2 bb = *(const ulonglong2*)&Bs[kk][tx << 2];
#pragma unroll
            for (int i = 0; i < 8; i++) {
                unsigned long long a =
                    *(const unsigned long long*)&As2[kk][((ty << 3) + i) << 1];
                ffma2(acc[i][0], a, bb.x);
                ffma2(acc[i][1], a, bb.y);
            }
        }
        __syncthreads();
    }

#pragma unroll
    for (int i = 0; i < 8; i++) {
        int row = tm + (ty << 3) + i;
#pragma unroll
        for (int j2 = 0; j2 < 2; j2++) {
            float v0, v1;
            unpack2(acc[i][j2], v0, v1);
            int col = tn + (tx << 2) + (j2 << 1);
            v0 += bias[col];
            v1 += bias[col + 1];
            if (mode == 0) {
                Cout[(size_t)row * N + col]     = v0;
                Cout[(size_t)row * N + col + 1] = v1;
            } else {
                int b_ = row / len, s_ = row - b_ * len;
                int h0 = col >> 6, d0 = col & 63;   // col even -> col,col+1 same head
                if (mode == 1) {
                    float* p = Cout + (((size_t)b_ * HH + h0) * len + s_) * DD + d0;
                    p[0] = v0; p[1] = v1;
                } else {
                    float* p = Cout + (((size_t)b_ * HH + h0) * DD + d0) * TT + s_;
                    p[0] = v0; p[TT] = v1;
                }
            }
        }
    }
}

// ============================================================================
// Flash-style attention: one CTA per (b, h, 64-row s-tile). Streams T in
// 64-chunks with online softmax; scores live in registers. Raw scaled scores
// are written to g_praw and per-row (m, invZ/H) to g_stat for the avg kernel.
// smem = 102.9 KB -> 2 CTAs/SM (16 warps).
//
// Layout (floats):
//   sQ2 [64][130]  Q duplicated-transposed: sQ2[d][2s]=(q,q)      8320
//   sK  [64][68]   K chunk, d-major rows                          4352
//   sV  [64][68]   V chunk, t-major rows                          4352
//   sP2 [64][136]  P duplicated: sP2[s][2t]=(p,p)                 8704
// ============================================================================
#define AT_SMEM_FLOATS (8320 + 4352 + 4352 + 8704)
#define AT_SMEM_BYTES  (AT_SMEM_FLOATS * 4)

__global__ __launch_bounds__(256, 2) void attn_flash_kernel(
    const float* __restrict__ q, const float* __restrict__ kdt,
    const float* __restrict__ v, float* __restrict__ ao,
    float* __restrict__ praw, float2* __restrict__ stat)
{
    extern __shared__ __align__(16) float sm[];
    float* sQ2 = sm;
    float* sK  = sm + 8320;
    float* sV  = sm + 12672;
    float* sP2 = sm + 17024;

    const int tid = threadIdx.x;
    const int tx = tid & 15;    // t (phase1) / d (phase3) dim, x4
    const int ty = tid >> 4;    // s dim, x4

    const int bh = blockIdx.x >> 5;              // SS/64 = 32 tiles per head
    const int st = (blockIdx.x & 31) << 6;
    const int b_ = bh >> 4;
    const int h_ = bh & 15;

    const float* qbase = q   + ((size_t)bh * SS + st) * DD;
    const float* kbase = kdt + (size_t)bh * DD * TT;
    const float* vbase = v   + (size_t)bh * TT * DD;

    // Load Q tile [64,64] duplicated-transposed: sQ2[d][2s] = (q,q)
#pragma unroll
    for (int i = 0; i < 4; i++) {
        int idx = tid + i * 256;
        int s_  = idx >> 4;
        int d4  = (idx & 15) << 2;
        float4 qv = *(const float4*)(qbase + (size_t)s_ * DD + d4);
        *(float2*)&sQ2[(d4 + 0) * 130 + (s_ << 1)] = make_float2(qv.x, qv.x);
        *(float2*)&sQ2[(d4 + 1) * 130 + (s_ << 1)] = make_float2(qv.y, qv.y);
        *(float2*)&sQ2[(d4 + 2) * 130 + (s_ << 1)] = make_float2(qv.z, qv.z);
        *(float2*)&sQ2[(d4 + 3) * 130 + (s_ << 1)] = make_float2(qv.w, qv.w);
    }

    unsigned long long oacc[4][2];
    float mrun[4], zrun[4];
#pragma unroll
    for (int i = 0; i < 4; i++) {
        oacc[i][0] = 0ULL; oacc[i][1] = 0ULL;
        mrun[i] = -1e30f;  zrun[i] = 0.f;
    }

    for (int c = 0; c < TT / 64; c++) {
        __syncthreads();   // prev-chunk PV reads of sK/sV done; (iter0: before K/V fill)
        // Load K chunk (d-major) and V chunk (t-major)
#pragma unroll
        for (int i = 0; i < 4; i++) {
            int idx = tid + i * 256;
            int r  = idx >> 4;
            int c4 = (idx & 15) << 2;
            *(float4*)&sK[r * 68 + c4] = *(const float4*)(kbase + (size_t)r * TT + c * 64 + c4);
            *(float4*)&sV[r * 68 + c4] = *(const float4*)(vbase + (size_t)(c * 64 + r) * DD + c4);
        }
        __syncthreads();

        // ---- QK^T chunk: S[64s x 64t], k-depth = 64 d ----
        unsigned long long sacc[4][2] = {{0ULL,0ULL},{0ULL,0ULL},{0ULL,0ULL},{0ULL,0ULL}};
#pragma unroll 16
        for (int kk = 0; kk < 64; kk++) {
            ulonglong2 bb = *(const ulonglong2*)&sK[kk * 68 + (tx << 2)];
#pragma unroll
            for (int i = 0; i < 4; i++) {
                unsigned long long a =
                    *(const unsigned long long*)&sQ2[kk * 130 + (((ty << 2) + i) << 1)];
                ffma2(sacc[i][0], a, bb.x);
                ffma2(sacc[i][1], a, bb.y);
            }
        }

        // ---- online softmax update + raw-score spill + P into smem ----
#pragma unroll
        for (int i = 0; i < 4; i++) {
            float v0, v1, v2, v3;
            unpack2(sacc[i][0], v0, v1);
            unpack2(sacc[i][1], v2, v3);
            v0 *= 0.125f; v1 *= 0.125f; v2 *= 0.125f; v3 *= 0.125f;   // 1/sqrt(64)

            int srow = st + (ty << 2) + i;
            *(float4*)&praw[((size_t)bh * SS + srow) * TT + c * 64 + (tx << 2)] =
                make_float4(v0, v1, v2, v3);

            float cm = fmaxf(fmaxf(v0, v1), fmaxf(v2, v3));
#pragma unroll
            for (int off = 8; off; off >>= 1)
                cm = fmaxf(cm, __shfl_xor_sync(0xffffffffu, cm, off));
            float mn   = fmaxf(mrun[i], cm);
            float corr = __expf(mrun[i] - mn);
            mrun[i] = mn;

            float p0 = __expf(v0 - mn), p1 = __expf(v1 - mn);
            float p2 = __expf(v2 - mn), p3 = __expf(v3 - mn);
            float zs = (p0 + p1) + (p2 + p3);
#pragma unroll
            for (int off = 8; off; off >>= 1)
                zs += __shfl_xor_sync(0xffffffffu, zs, off);
            zrun[i] = zrun[i] * corr + zs;

            unsigned long long cc = pack2(corr, corr);
            fmul2(oacc[i][0], cc);
            fmul2(oacc[i][1], cc);

            float* pp = &sP2[(size_t)((ty << 2) + i) * 136 + (tx << 3)];
            *(float4*)pp       = make_float4(p0, p0, p1, p1);
            *(float4*)(pp + 4) = make_float4(p2, p2, p3, p3);
        }
        __syncwarp();   // sP2 rows are produced & consumed within one half-warp

        // ---- PV chunk: out += P[64s x 64t] @ V[64t x 64d] ----
#pragma unroll 16
        for (int kk = 0; kk < 64; kk++) {
            ulonglong2 vv = *(const ulonglong2*)&sV[kk * 68 + (tx << 2)];
#pragma unroll
            for (int i = 0; i < 4; i++) {
                unsigned long long a =
                    *(const unsigned long long*)&sP2[(size_t)((ty << 2) + i) * 136 + (kk << 1)];
                ffma2(oacc[i][0], a, vv.x);
                ffma2(oacc[i][1], a, vv.y);
            }
        }
    }

    // ---- epilogue: normalize, write out head-slice + per-row stats ----
#pragma unroll
    for (int i = 0; i < 4; i++) {
        float inv = 1.0f / zrun[i];
        float v0, v1, v2, v3;
        unpack2(oacc[i][0], v0, v1);
        unpack2(oacc[i][1], v2, v3);
        int srow = st + (ty << 2) + i;
        float* p = ao + ((size_t)b_ * SS + srow) * EE + h_ * DD + (tx << 2);
        *(float4*)p = make_float4(v0 * inv, v1 * inv, v2 * inv, v3 * inv);
        if (tx == 0)
            stat[(size_t)bh * SS + srow] = make_float2(mrun[i], inv * (1.0f / (float)HH));
    }
}

// ============================================================================
// avg_attn: avg[b,s,t] = (1/H) sum_h exp(praw[b,h,s,t] - m[bh,s]) * invZ[bh,s]
// Pure memory-bound pass over 1.07 GB; no atomics.
// ============================================================================
__global__ __launch_bounds__(256) void avg_kernel(
    const float* __restrict__ praw, const float2* __restrict__ stat,
    float* __restrict__ avg)
{
    size_t gi = (size_t)blockIdx.x * 256 + threadIdx.x;    // over B*S*(T/4)
    int    t4 = (int)(gi & (TT / 4 - 1)) << 2;
    size_t bs = gi >> 8;                                    // / (T/4)
    int b_ = (int)(bs >> 11);                               // / SS
    int s_ = (int)(bs & (SS - 1));

    float a0 = 0.f, a1 = 0.f, a2 = 0.f, a3 = 0.f;
#pragma unroll
    for (int h = 0; h < HH; h++) {
        size_t row = ((size_t)(b_ * HH + h) * SS + s_);
        float2 mz = stat[row];
        float4 r  = *(const float4*)&praw[row * TT + t4];
        a0 += __expf(r.x - mz.x) * mz.y;
        a1 += __expf(r.y - mz.x) * mz.y;
        a2 += __expf(r.z - mz.x) * mz.y;
        a3 += __expf(r.w - mz.x) * mz.y;
    }
    *(float4*)&avg[bs * TT + t4] = make_float4(a0, a1, a2, a3);
}

// ============================================================================
// Launch
// ============================================================================
extern "C" void kernel_launch(void* const* d_in, const int* in_sizes, int n_in,
                              void* d_out, int out_size)
{
    const float* x   = (const float*)d_in[0];
    const float* enc = (const float*)d_in[1];
    const float* Wq  = (const float*)d_in[2];
    const float* bq  = (const float*)d_in[3];
    const float* Wk  = (const float*)d_in[4];
    const float* bk  = (const float*)d_in[5];
    const float* Wv  = (const float*)d_in[6];
    const float* bv  = (const float*)d_in[7];
    const float* Wo  = (const float*)d_in[8];
    const float* bo  = (const float*)d_in[9];

    float* out = (float*)d_out;                       // [B,S,E]
    float* avg = out + (size_t)BB * SS * EE;          // [B,S,T]

    float *qp, *kp, *vp, *aop, *prp;
    float2* stp;
    cudaGetSymbolAddress((void**)&qp,  g_q);
    cudaGetSymbolAddress((void**)&kp,  g_k);
    cudaGetSymbolAddress((void**)&vp,  g_v);
    cudaGetSymbolAddress((void**)&aop, g_ao);
    cudaGetSymbolAddress((void**)&prp, g_praw);
    cudaGetSymbolAddress((void**)&stp, g_stat);

    cudaFuncSetAttribute(attn_flash_kernel,
                         cudaFuncAttributeMaxDynamicSharedMemorySize, AT_SMEM_BYTES);

    // Q = x @ Wq + bq        -> [B,H,S,D]
    gemm_bias_kernel<<<dim3(EE / 64, (BB * SS) / 128), 256>>>(x,   Wq, bq, qp,  BB * SS, EE, EE, SS, 1);
    // K = enc @ Wk + bk      -> [B,H,D,T] (d-major)
    gemm_bias_kernel<<<dim3(EE / 64, (BB * TT) / 128), 256>>>(enc, Wk, bk, kp,  BB * TT, CC, EE, TT, 2);
    // V = enc @ Wv + bv      -> [B,H,T,D]
    gemm_bias_kernel<<<dim3(EE / 64, (BB * TT) / 128), 256>>>(enc, Wv, bv, vp,  BB * TT, CC, EE, TT, 1);
    // flash attention (writes g_ao, g_praw, g_stat)
    attn_flash_kernel<<<BB * HH * (SS / 64), 256, AT_SMEM_BYTES>>>(qp, kp, vp, aop, prp, stp);
    // avg_attn from raw scores + stats
    avg_kernel<<<(unsigned)((size_t)BB * SS * (TT / 4) / 256), 256>>>(prp, stp, avg);
    // out = attn_out @ Wo + bo
    gemm_bias_kernel<<<dim3(EE / 64, (BB * SS) / 128), 256>>>(aop, Wo, bo, out, BB * SS, EE, EE, 0, 0);
}